// round 10
// baseline (speedup 1.0000x reference)
#include <cuda_runtime.h>
#include <cuda_bf16.h>

// Distance_26379689132772: dense radius_graph over N=8192 atoms, 128 atoms/mol.
// Output layout (f32): [0, N*N) edge_weight ; [N*N, 2*N*N) mask (0/1).
//
// R8 measurement: the memset fill path writes at ~7.3 TB/s vs ~6.8 TB/s for
// SM STG kernels. Strategy: zero everything via memset nodes, and hide the
// tiny diagonal-block kernels under later memsets via fork-join capture.
//   - memset W plane; diagW (forked stream) hides under the M memsets.
//   - memset M plane in 4 slabs; diagM chunk k hides under slab k+1.
//   - exposed tail = last diagM chunk (~1us).

#define NATOMS 8192
#define CUT_HI 5.0f
#define NN     ((size_t)NATOMS * NATOMS)   // floats per plane
#define MOL    128

// Writes the diagonal 128x128 blocks of ONE plane for molecules
// [mol0, mol0 + grid/16). One block = 8 rows of one molecule's diag block;
// warp w -> row, lane -> 4 columns (one float4).
__global__ __launch_bounds__(256)
void diag_plane_kernel(const float* __restrict__ pos,
                       float*       __restrict__ plane,
                       int mol0, int want_w)
{
    int mol    = mol0 + (int)(blockIdx.x >> 4);
    int rowgrp = (int)(blockIdx.x & 15u);
    int w      = (int)(threadIdx.x >> 5);
    int lane   = (int)(threadIdx.x & 31u);

    int i  = mol * MOL + rowgrp * 8 + w;     // global row
    int j0 = mol * MOL + lane * 4;           // global col of this lane's quad

    float xi = __ldg(pos + 3 * i + 0);
    float yi = __ldg(pos + 3 * i + 1);
    float zi = __ldg(pos + 3 * i + 2);
    float sqi = xi * xi + yi * yi + zi * zi;

    float v[4];
    #pragma unroll
    for (int k = 0; k < 4; k++) {
        int jj = j0 + k;
        float xj = __ldg(pos + 3 * jj + 0);
        float yj = __ldg(pos + 3 * jj + 1);
        float zj = __ldg(pos + 3 * jj + 2);
        float sqj = xj * xj + yj * yj + zj * zj;
        // Gram trick, matching the reference's arithmetic path.
        float d2 = sqi + sqj - 2.0f * (xi * xj + yi * yj + zi * zj);
        d2 = fmaxf(d2, 0.0f);
        float d = (d2 > 0.0f) ? sqrtf(d2) : 0.0f;
        bool mask = (i != jj) && (d <= CUT_HI);
        v[k] = mask ? (want_w ? d : 1.0f) : 0.0f;
    }

    *(float4*)(plane + (size_t)i * NATOMS + j0) = make_float4(v[0], v[1], v[2], v[3]);
}

extern "C" void kernel_launch(void* const* d_in, const int* in_sizes, int n_in,
                              void* d_out, int out_size)
{
    const float* pos = (const float*)d_in[0];
    float*       out = (float*)d_out;
    float*       M   = out + NN;             // mask plane base

    // One-time host-object init (streams/events only; the GPU work enqueued
    // below is identical on every call -> deterministic).
    static cudaStream_t s1 = nullptr;
    static cudaEvent_t  eW, eM0, eM1, eM2, eJ;
    if (s1 == nullptr) {
        cudaStreamCreateWithFlags(&s1, cudaStreamNonBlocking);
        cudaEventCreateWithFlags(&eW,  cudaEventDisableTiming);
        cudaEventCreateWithFlags(&eM0, cudaEventDisableTiming);
        cudaEventCreateWithFlags(&eM1, cudaEventDisableTiming);
        cudaEventCreateWithFlags(&eM2, cudaEventDisableTiming);
        cudaEventCreateWithFlags(&eJ,  cudaEventDisableTiming);
    }

    const size_t SLAB = NN / 4;              // 16 molecules of the mask plane

    // Main (capture) stream: fill path.
    cudaMemsetAsync(out,            0, NN   * sizeof(float));   // W plane
    cudaEventRecord(eW, 0);
    cudaMemsetAsync(M,              0, SLAB * sizeof(float));   // M mols  0-15
    cudaEventRecord(eM0, 0);
    cudaMemsetAsync(M + 1 * SLAB,   0, SLAB * sizeof(float));   // M mols 16-31
    cudaEventRecord(eM1, 0);
    cudaMemsetAsync(M + 2 * SLAB,   0, SLAB * sizeof(float));   // M mols 32-47
    cudaEventRecord(eM2, 0);
    cudaMemsetAsync(M + 3 * SLAB,   0, SLAB * sizeof(float));   // M mols 48-63

    // Forked stream: diagonal writes, hidden under later memsets.
    cudaStreamWaitEvent(s1, eW, 0);
    diag_plane_kernel<<<64 * 16, 256, 0, s1>>>(pos, out, 0, 1); // W diag, all mols
    cudaStreamWaitEvent(s1, eM0, 0);
    diag_plane_kernel<<<16 * 16, 256, 0, s1>>>(pos, M,  0, 0);  // M diag  0-15
    cudaStreamWaitEvent(s1, eM1, 0);
    diag_plane_kernel<<<16 * 16, 256, 0, s1>>>(pos, M, 16, 0);  // M diag 16-31
    cudaStreamWaitEvent(s1, eM2, 0);
    diag_plane_kernel<<<16 * 16, 256, 0, s1>>>(pos, M, 32, 0);  // M diag 32-47
    cudaEventRecord(eJ, s1);

    // Join, then exposed tail: last M diag chunk (after M slab 3 by stream order).
    cudaStreamWaitEvent(0, eJ, 0);
    diag_plane_kernel<<<16 * 16, 256>>>(pos, M, 48, 0);         // M diag 48-63
}

// round 11
// speedup vs baseline: 1.0961x; 1.0961x over previous
#include <cuda_runtime.h>
#include <cuda_bf16.h>

// Distance_26379689132772: dense radius_graph over N=8192 atoms, 128 atoms/mol.
// Output layout (f32): [0, N*N) edge_weight ; [N*N, 2*N*N) mask (0/1).
//
// Concurrent split, minimal graph nodes:
//   stream 0 : SM kernel writes full W plane (256MB, computed)
//   stream s1: cudaMemset zeros full M plane (256MB, ~7.3 TB/s fill path)
//   stream 0 : after join, tiny diagM kernel writes mask diag blocks (4MB)
// If the fill path is copy-engine-backed, the two 256MB writes overlap and
// the total approaches the HBM aggregate write ceiling.

#define NATOMS 8192
#define CUT_HI 5.0f
#define NN     ((size_t)NATOMS * NATOMS)   // floats per plane
#define MOL    128
#define QUADS  (NATOMS * NATOMS / 4)       // float4s per plane

// ---------- W plane: full dense weight matrix (R4-proven store pattern) ----
__device__ __forceinline__ void compute_quad_w(const float* __restrict__ pos,
                                               const int*   __restrict__ batch,
                                               unsigned idx, float4& ew)
{
    int i = (int)(idx >> 11);            // idx / 2048
    int j = (int)((idx & 2047u) << 2);   // 4*(idx % 2048)

    ew = make_float4(0.f, 0.f, 0.f, 0.f);

    int bi = __ldg(batch + i);
    int bj = __ldg(batch + j);

    if (bi == bj) {
        float xi = __ldg(pos + 3 * i + 0);
        float yi = __ldg(pos + 3 * i + 1);
        float zi = __ldg(pos + 3 * i + 2);
        float sqi = xi * xi + yi * yi + zi * zi;

        float w[4];
        #pragma unroll
        for (int k = 0; k < 4; k++) {
            int jj = j + k;
            float xj = __ldg(pos + 3 * jj + 0);
            float yj = __ldg(pos + 3 * jj + 1);
            float zj = __ldg(pos + 3 * jj + 2);
            float sqj = xj * xj + yj * yj + zj * zj;
            float d2 = sqi + sqj - 2.0f * (xi * xj + yi * yj + zi * zj);
            d2 = fmaxf(d2, 0.0f);
            float d = (d2 > 0.0f) ? sqrtf(d2) : 0.0f;
            bool mask = (i != jj) && (d <= CUT_HI);
            w[k] = mask ? d : 0.0f;
        }
        ew = make_float4(w[0], w[1], w[2], w[3]);
    }
}

__global__ __launch_bounds__(256)
void wplane_kernel(const float* __restrict__ pos,
                   const int*   __restrict__ batch,
                   float*       __restrict__ out)
{
    float4* __restrict__ ow = (float4*)out;
    // Block covers 512 consecutive quads; thread t handles t and t+256.
    unsigned base = blockIdx.x * 512u + threadIdx.x;
    float4 e0, e1;
    compute_quad_w(pos, batch, base,        e0);
    compute_quad_w(pos, batch, base + 256u, e1);
    ow[base]        = e0;
    ow[base + 256u] = e1;
}

// ---------- M plane diagonal blocks (after memset zeroed the plane) --------
__global__ __launch_bounds__(256)
void diag_mask_kernel(const float* __restrict__ pos,
                      float*       __restrict__ mplane)
{
    int mol    = (int)(blockIdx.x >> 4);          // 0..63
    int rowgrp = (int)(blockIdx.x & 15u);         // 0..15
    int w      = (int)(threadIdx.x >> 5);
    int lane   = (int)(threadIdx.x & 31u);

    int i  = mol * MOL + rowgrp * 8 + w;
    int j0 = mol * MOL + lane * 4;

    float xi = __ldg(pos + 3 * i + 0);
    float yi = __ldg(pos + 3 * i + 1);
    float zi = __ldg(pos + 3 * i + 2);
    float sqi = xi * xi + yi * yi + zi * zi;

    float v[4];
    #pragma unroll
    for (int k = 0; k < 4; k++) {
        int jj = j0 + k;
        float xj = __ldg(pos + 3 * jj + 0);
        float yj = __ldg(pos + 3 * jj + 1);
        float zj = __ldg(pos + 3 * jj + 2);
        float sqj = xj * xj + yj * yj + zj * zj;
        float d2 = sqi + sqj - 2.0f * (xi * xj + yi * yj + zi * zj);
        d2 = fmaxf(d2, 0.0f);
        float d = (d2 > 0.0f) ? sqrtf(d2) : 0.0f;
        bool mask = (i != jj) && (d <= CUT_HI);
        v[k] = mask ? 1.0f : 0.0f;
    }

    *(float4*)(mplane + (size_t)i * NATOMS + j0) = make_float4(v[0], v[1], v[2], v[3]);
}

extern "C" void kernel_launch(void* const* d_in, const int* in_sizes, int n_in,
                              void* d_out, int out_size)
{
    const float* pos   = (const float*)d_in[0];
    const int*   batch = (const int*)d_in[1];
    float*       out   = (float*)d_out;
    float*       M     = out + NN;

    static cudaStream_t s1 = nullptr;
    static cudaEvent_t  eFork, eJoin;
    if (s1 == nullptr) {
        cudaStreamCreateWithFlags(&s1, cudaStreamNonBlocking);
        cudaEventCreateWithFlags(&eFork, cudaEventDisableTiming);
        cudaEventCreateWithFlags(&eJoin, cudaEventDisableTiming);
    }

    // Fork: M-plane memset runs concurrently with the W-plane SM kernel.
    cudaEventRecord(eFork, 0);
    cudaStreamWaitEvent(s1, eFork, 0);
    cudaMemsetAsync(M, 0, NN * sizeof(float), s1);      // 256MB fill path
    cudaEventRecord(eJoin, s1);

    wplane_kernel<<<QUADS / 512, 256>>>(pos, batch, out);  // 256MB SM stores

    // Join, then mask diag blocks (must follow the memset).
    cudaStreamWaitEvent(0, eJoin, 0);
    diag_mask_kernel<<<64 * 16, 256>>>(pos, M);
}